// round 1
// baseline (speedup 1.0000x reference)
#include <cuda_runtime.h>
#include <math.h>

// ---------------------------------------------------------------------------
// LaCT SWIGLU fast-weight self-attention, fp32 SIMT baseline.
// BH=8, T=4096, D=DI=512, CS=256. 15 update chunks + 1 forward-only chunk.
// All GEMMs go through one generic strided NT-form kernel:
//   C[r,c] = alpha * sum_k A(r,k)*B(c,k)  (+ beta * Dm[r,c])
// Symmetry of X@X^T and A@A is exact (identical FMA order), so every
// Newton-Schulz GEMM is NT-form too.
// ---------------------------------------------------------------------------

#define BH 8
#define TT 4096
#define DD 512
#define DI 512
#define CS 256
#define NCHUNK 15          // T/CS - 1
#define NMAT 24            // 3 weights * BH
#define MSZ (512 * 512)    // elements per weight matrix
#define EW1_N (BH * DI * CS)
#define EW2_N (BH * CS * DD)

// ------------------------- device scratch ----------------------------------
__device__ float g_wm[NMAT][MSZ];     // momentum-accumulated (unnormalized) weights
__device__ float g_wc[NMAT][MSZ];     // current (normalized) weights used in fwd/bwd
__device__ float g_dm[NMAT][MSZ];     // momentum buffer (= previous dw)
__device__ float g_dw[NMAT][MSZ];     // raw grads from this chunk
__device__ float g_wnorm[NMAT][512];  // original per-row norms
__device__ float g_X0[NMAT][MSZ];     // NS ping
__device__ float g_X1[NMAT][MSZ];     // NS pong
__device__ float g_Ab[NMAT][MSZ];     // NS A = X X^T
__device__ float g_Bb[NMAT][MSZ];     // NS B = b*A + c*A*A

__device__ float g_gba[EW1_N];        // w0c @ k^T
__device__ float g_hbm[EW1_N];        // w2c @ k^T
__device__ float g_hh[EW1_N];         // w2c @ q^T
__device__ float g_g0[EW1_N];         // w0c @ q^T
__device__ float g_dhid[EW1_N];       // w1c^T @ v^T
__device__ float g_gh[EW1_N];         // silu(g0)*h
__device__ float g_hl1[EW1_N];        // hidden * l1
__device__ float g_dhbm[EW1_N];
__device__ float g_dgba[EW1_N];
__device__ float g_kl0[EW2_N];        // k * lr0
__device__ float g_kl2[EW2_N];        // k * lr2
__device__ float g_mi[BH];
__device__ float g_mli[BH];
__device__ float g_rns[NMAT];         // 1/(frob(dm)+1e-7)

// ------------------------- generic GEMM ------------------------------------
struct GArgs {
    const float* A; int asr, ask; long abs_;
    const float* B; int bsr, bsk; long bbs;
    float*       C; int csr, csc; long cbs;
    const float* Dm; long dbs;         // Dm shares C's (csr,csc)
    int K;
    float alpha, beta;
};

// 128x128 tile, TK=8, 256 threads, 8x8 per thread (two 4x4 quads).
__global__ __launch_bounds__(256, 2) void gemm_k(GArgs g) {
    __shared__ __align__(16) float As[8][132];  // pad 132 -> conflict-free STS
    __shared__ __align__(16) float Bs[8][132];

    const int b = blockIdx.z;
    const float* A = g.A + (long)b * g.abs_;
    const float* B = g.B + (long)b * g.bbs;
    const int row0 = blockIdx.y * 128;
    const int col0 = blockIdx.x * 128;
    const int tid = threadIdx.x;
    const int tx = tid & 15, ty = tid >> 4;

    float acc[8][8];
#pragma unroll
    for (int i = 0; i < 8; i++)
#pragma unroll
        for (int j = 0; j < 8; j++) acc[i][j] = 0.f;

    const bool aKfast = (g.ask == 1);
    const bool bKfast = (g.bsk == 1);

    for (int kt = 0; kt < g.K; kt += 8) {
        if (aKfast) {
            int kk = tid & 7, r = tid >> 3;  // 32 rows/pass
            const float* p = A + (long)(row0 + r) * g.asr + (kt + kk);
#pragma unroll
            for (int ps = 0; ps < 4; ps++)
                As[kk][r + ps * 32] = p[(long)ps * 32 * g.asr];
        } else {  // row-contiguous operand (asr expected 1)
            int r = tid & 127, kk = tid >> 7;  // 2 k/pass
            const float* p = A + (long)(kt + kk) * g.ask + (long)(row0 + r) * g.asr;
#pragma unroll
            for (int ps = 0; ps < 4; ps++)
                As[kk + ps * 2][r] = p[(long)ps * 2 * g.ask];
        }
        if (bKfast) {
            int kk = tid & 7, c = tid >> 3;
            const float* p = B + (long)(col0 + c) * g.bsr + (kt + kk);
#pragma unroll
            for (int ps = 0; ps < 4; ps++)
                Bs[kk][c + ps * 32] = p[(long)ps * 32 * g.bsr];
        } else {
            int c = tid & 127, kk = tid >> 7;
            const float* p = B + (long)(kt + kk) * g.bsk + (long)(col0 + c) * g.bsr;
#pragma unroll
            for (int ps = 0; ps < 4; ps++)
                Bs[kk + ps * 2][c] = p[(long)ps * 2 * g.bsk];
        }
        __syncthreads();
#pragma unroll
        for (int kk = 0; kk < 8; kk++) {
            float4 a0 = *reinterpret_cast<const float4*>(&As[kk][ty * 4]);
            float4 a1 = *reinterpret_cast<const float4*>(&As[kk][64 + ty * 4]);
            float4 b0 = *reinterpret_cast<const float4*>(&Bs[kk][tx * 4]);
            float4 b1 = *reinterpret_cast<const float4*>(&Bs[kk][64 + tx * 4]);
            float av[8] = {a0.x, a0.y, a0.z, a0.w, a1.x, a1.y, a1.z, a1.w};
            float bv[8] = {b0.x, b0.y, b0.z, b0.w, b1.x, b1.y, b1.z, b1.w};
#pragma unroll
            for (int i = 0; i < 8; i++)
#pragma unroll
                for (int j = 0; j < 8; j++) acc[i][j] += av[i] * bv[j];
        }
        __syncthreads();
    }

    float* C = g.C + (long)b * g.cbs;
    const float* Dm = g.Dm ? (g.Dm + (long)b * g.dbs) : (const float*)0;
#pragma unroll
    for (int i = 0; i < 8; i++) {
        int r = row0 + ((i < 4) ? (ty * 4 + i) : (64 + ty * 4 + (i - 4)));
#pragma unroll
        for (int j = 0; j < 8; j++) {
            int c = col0 + ((j < 4) ? (tx * 4 + j) : (64 + tx * 4 + (j - 4)));
            long off = (long)r * g.csr + (long)c * g.csc;
            float val = g.alpha * acc[i][j];
            if (Dm) val += g.beta * Dm[off];
            C[off] = val;
        }
    }
}

// ------------------------- elementwise kernels ------------------------------
__device__ __forceinline__ float sigf(float x) { return 1.f / (1.f + expf(-x)); }

__global__ void k_init(const float* w0, const float* w1, const float* w2) {
    int row = blockIdx.x;          // NMAT*512 rows
    int m = row >> 9;
    int w = m >> 3;
    int bh = m & 7;
    int r = row & 511;
    const float* src = (w == 0 ? w0 : (w == 1 ? w1 : w2)) + (long)bh * MSZ + (long)r * 512;
    float* wm = &g_wm[m][r * 512];
    float* wc = &g_wc[m][r * 512];
    float* dm = &g_dm[m][r * 512];
    int t = threadIdx.x;
    float ss = 0.f;
#pragma unroll
    for (int j = 0; j < 4; j++) {
        int c = t + j * 128;
        float v = src[c];
        wm[c] = v; wc[c] = v; dm[c] = 0.f;
        ss += v * v;
    }
    __shared__ float red[128];
    red[t] = ss; __syncthreads();
    for (int s = 64; s > 0; s >>= 1) { if (t < s) red[t] += red[t + s]; __syncthreads(); }
    if (t == 0) g_wnorm[m][r] = sqrtf(red[0]);
}

__global__ void k_ew1(const float* lr1, int cbase) {
    int idx = blockIdx.x * 256 + threadIdx.x;
    int t = idx & (CS - 1);
    int bh = idx / (DI * CS);
    float gba = g_gba[idx];
    float hbm = g_hbm[idx];
    float dh  = g_dhid[idx];
    float sg = sigf(gba);
    float sil = gba * sg;
    float hidden = sil * hbm;
    float l1 = lr1[(long)bh * TT + cbase + t];
    g_hl1[idx]  = hidden * l1;
    g_dhbm[idx] = dh * sil;
    float dgate = dh * hbm;
    g_dgba[idx] = dgate * sg * (1.f + gba * (1.f - sg));
    float g0v = g_g0[idx];
    float hv  = g_hh[idx];
    float sq = sigf(g0v);
    g_gh[idx] = g0v * sq * hv;
}

__global__ void k_ew2(const float* kin, const float* lr0, const float* lr2, int cbase) {
    int idx = blockIdx.x * 256 + threadIdx.x;
    int c = idx & (DD - 1);
    int t = (idx >> 9) & (CS - 1);
    int bh = idx / (CS * DD);
    float kv = kin[(long)bh * TT * DD + (long)(cbase + t) * DD + c];
    float l0 = lr0[(long)bh * TT + cbase + t];
    float l2 = lr2[(long)bh * TT + cbase + t];
    g_kl0[idx] = kv * l0;
    g_kl2[idx] = kv * l2;
}

__global__ void k_ewfwd() {
    int idx = blockIdx.x * 256 + threadIdx.x;
    float g0v = g_g0[idx];
    float hv  = g_hh[idx];
    float sq = sigf(g0v);
    g_gh[idx] = g0v * sq * hv;
}

__global__ void k_scalars(const float* mom, const float* mlt, int cbase) {
    int bh = blockIdx.x;
    int t = threadIdx.x;  // 256
    __shared__ float r1[256], r2[256];
    r1[t] = mom[(long)bh * TT + cbase + t];
    r2[t] = mlt[(long)bh * TT + cbase + t];
    __syncthreads();
    for (int s = 128; s > 0; s >>= 1) {
        if (t < s) { r1[t] += r1[t + s]; r2[t] += r2[t + s]; }
        __syncthreads();
    }
    if (t == 0) { g_mi[bh] = r1[0] * (1.f / CS); g_mli[bh] = r2[0] * (1.f / CS); }
}

__global__ void k_dwupd() {
    int idx = blockIdx.x * 256 + threadIdx.x;  // NMAT*MSZ exact
    int m = idx >> 18;                          // MSZ = 2^18
    int bh = m & 7;
    float* dmf = &g_dm[0][0];
    const float* dwf = &g_dw[0][0];
    float v = dwf[idx] + dmf[idx] * g_mi[bh];
    dmf[idx] = v;
}

__global__ void k_norm24() {
    int m = blockIdx.x;
    int t = threadIdx.x;  // 256
    const float* p = g_dm[m];
    float s = 0.f;
    for (int i = t; i < MSZ; i += 256) { float v = p[i]; s += v * v; }
    __shared__ float red[256];
    red[t] = s; __syncthreads();
    for (int st = 128; st > 0; st >>= 1) { if (t < st) red[t] += red[t + st]; __syncthreads(); }
    if (t == 0) g_rns[m] = 1.f / (sqrtf(red[0]) + 1e-7f);
}

__global__ void k_xscale() {
    int idx = blockIdx.x * 256 + threadIdx.x;
    int m = idx >> 18;
    (&g_X0[0][0])[idx] = (&g_dm[0][0])[idx] * g_rns[m];
}

__global__ void k_wupd(const float* X) {
    int row = blockIdx.x;
    int m = row >> 9;
    int bh = m & 7;
    int r = row & 511;
    const float* x = X + (long)m * MSZ + (long)r * 512;
    float* wm = &g_wm[m][r * 512];
    float ml = g_mli[bh];
    int t = threadIdx.x;  // 128
    float vals[4];
    float ss = 0.f;
#pragma unroll
    for (int j = 0; j < 4; j++) {
        int c = t + j * 128;
        float v = wm[c] + x[c] * ml;
        wm[c] = v; vals[j] = v;
        ss += v * v;
    }
    __shared__ float red[128];
    red[t] = ss; __syncthreads();
    for (int s = 64; s > 0; s >>= 1) { if (t < s) red[t] += red[t + s]; __syncthreads(); }
    float scale = g_wnorm[m][r] / (sqrtf(red[0]) + 1e-5f);
#pragma unroll
    for (int j = 0; j < 4; j++) {
        int c = t + j * 128;
        g_wc[m][r * 512 + c] = vals[j] * scale;
    }
}

// ------------------------- host orchestration -------------------------------
static void launch_gemm(const float* A, int asr, int ask, long abs_,
                        const float* B, int bsr, int bsk, long bbs,
                        float* C, int csr, int csc, long cbs,
                        const float* Dm, long dbs,
                        int M, int N, int K, float alpha, float beta, int batch) {
    GArgs g;
    g.A = A; g.asr = asr; g.ask = ask; g.abs_ = abs_;
    g.B = B; g.bsr = bsr; g.bsk = bsk; g.bbs = bbs;
    g.C = C; g.csr = csr; g.csc = csc; g.cbs = cbs;
    g.Dm = Dm; g.dbs = dbs;
    g.K = K; g.alpha = alpha; g.beta = beta;
    dim3 grid(N / 128, M / 128, batch);
    gemm_k<<<grid, 256>>>(g);
}

static const float NSC[5][3] = {
    {4.0848f, -6.8946f, 2.927f},
    {3.9505f, -6.3029f, 2.6377f},
    {3.7418f, -5.5913f, 2.3037f},
    {2.8769f, -3.1427f, 1.2046f},
    {2.8366f, -3.0525f, 1.2012f}};

extern "C" void kernel_launch(void* const* d_in, const int* in_sizes, int n_in,
                              void* d_out, int out_size) {
    const float* w0  = (const float*)d_in[0];
    const float* w1  = (const float*)d_in[1];
    const float* w2  = (const float*)d_in[2];
    const float* q   = (const float*)d_in[3];
    const float* kin = (const float*)d_in[4];
    const float* v   = (const float*)d_in[5];
    const float* lr0 = (const float*)d_in[6];
    const float* lr1 = (const float*)d_in[7];
    const float* lr2 = (const float*)d_in[8];
    const float* mom = (const float*)d_in[9];
    const float* mlt = (const float*)d_in[10];
    float* out = (float*)d_out;

    float *p_wc, *p_dw, *p_X0, *p_X1, *p_Ab, *p_Bb;
    float *p_gba, *p_hbm, *p_hh, *p_g0, *p_dhid, *p_gh, *p_hl1, *p_dhbm, *p_dgba, *p_kl0, *p_kl2;
    cudaGetSymbolAddress((void**)&p_wc, g_wc);
    cudaGetSymbolAddress((void**)&p_dw, g_dw);
    cudaGetSymbolAddress((void**)&p_X0, g_X0);
    cudaGetSymbolAddress((void**)&p_X1, g_X1);
    cudaGetSymbolAddress((void**)&p_Ab, g_Ab);
    cudaGetSymbolAddress((void**)&p_Bb, g_Bb);
    cudaGetSymbolAddress((void**)&p_gba, g_gba);
    cudaGetSymbolAddress((void**)&p_hbm, g_hbm);
    cudaGetSymbolAddress((void**)&p_hh, g_hh);
    cudaGetSymbolAddress((void**)&p_g0, g_g0);
    cudaGetSymbolAddress((void**)&p_dhid, g_dhid);
    cudaGetSymbolAddress((void**)&p_gh, g_gh);
    cudaGetSymbolAddress((void**)&p_hl1, g_hl1);
    cudaGetSymbolAddress((void**)&p_dhbm, g_dhbm);
    cudaGetSymbolAddress((void**)&p_dgba, g_dgba);
    cudaGetSymbolAddress((void**)&p_kl0, g_kl0);
    cudaGetSymbolAddress((void**)&p_kl2, g_kl2);

    const long WBS = (long)BH * MSZ;         // per-weight block of 8 matrices
    const long IBS = (long)DI * CS;          // intermediate batch stride
    const long TDS = (long)TT * DD;          // token-tensor batch stride
    const long KBS = (long)CS * DD;

    k_init<<<NMAT * 512, 128>>>(w0, w1, w2);

    for (int ci = 0; ci < NCHUNK; ci++) {
        int cb = ci * CS;
        const float* kcb = kin + (long)cb * DD;
        const float* qcb = q + (long)cb * DD;
        const float* vcb = v + (long)cb * DD;

        // gba = w0c @ k^T ; hbm = w2c @ k^T ; h = w2c @ q^T ; g0 = w0c @ q^T
        launch_gemm(p_wc,            DD, 1, MSZ, kcb, DD, 1, TDS, p_gba, CS, 1, IBS, 0, 0, DI, CS, DD, 1.f, 0.f, BH);
        launch_gemm(p_wc + 2 * WBS,  DD, 1, MSZ, kcb, DD, 1, TDS, p_hbm, CS, 1, IBS, 0, 0, DI, CS, DD, 1.f, 0.f, BH);
        launch_gemm(p_wc + 2 * WBS,  DD, 1, MSZ, qcb, DD, 1, TDS, p_hh,  CS, 1, IBS, 0, 0, DI, CS, DD, 1.f, 0.f, BH);
        launch_gemm(p_wc,            DD, 1, MSZ, qcb, DD, 1, TDS, p_g0,  CS, 1, IBS, 0, 0, DI, CS, DD, 1.f, 0.f, BH);
        // dhidden = w1c^T @ v^T
        launch_gemm(p_wc + 1 * WBS,  1, DI, MSZ, vcb, DD, 1, TDS, p_dhid, CS, 1, IBS, 0, 0, DI, CS, DD, 1.f, 0.f, BH);

        k_ew1<<<EW1_N / 256, 256>>>(lr1, cb);
        k_ew2<<<EW2_N / 256, 256>>>(kin, lr0, lr2, cb);

        // chunk_out = w1c @ (gate*h) -> written straight into d_out[bh, cb.., :]
        launch_gemm(p_wc + 1 * WBS, DI, 1, MSZ, p_gh, 1, CS, IBS,
                    out + (long)cb * DD, 1, DD, TDS, 0, 0, DD, CS, DI, 1.f, 0.f, BH);
        // dw1 = v^T @ (hidden^T * l1)
        launch_gemm(vcb, 1, DD, TDS, p_hl1, CS, 1, IBS,
                    p_dw + 1 * WBS, DI, 1, MSZ, 0, 0, DD, DI, CS, 1.f, 0.f, BH);
        // dw0 = dgba @ (k*l0)
        launch_gemm(p_dgba, CS, 1, IBS, p_kl0, 1, DD, KBS,
                    p_dw, DD, 1, MSZ, 0, 0, DI, DD, CS, 1.f, 0.f, BH);
        // dw2 = dhbm @ (k*l2)
        launch_gemm(p_dhbm, CS, 1, IBS, p_kl2, 1, DD, KBS,
                    p_dw + 2 * WBS, DD, 1, MSZ, 0, 0, DI, DD, CS, 1.f, 0.f, BH);

        k_scalars<<<BH, 256>>>(mom, mlt, cb);
        k_dwupd<<<NMAT * MSZ / 256, 256>>>();
        k_norm24<<<NMAT, 256>>>();
        k_xscale<<<NMAT * MSZ / 256, 256>>>();

        // Newton-Schulz (5 iters, 24 matrices). A and A@A are exactly symmetric.
        float* Xa = p_X0;
        float* Xb = p_X1;
        for (int it = 0; it < 5; it++) {
            float a = NSC[it][0], bcoef = NSC[it][1], ccoef = NSC[it][2];
            // A = X @ X^T
            launch_gemm(Xa, 512, 1, MSZ, Xa, 512, 1, MSZ, p_Ab, 512, 1, MSZ,
                        0, 0, 512, 512, 512, 1.f, 0.f, NMAT);
            // B = b*A + c*(A@A)   (A symmetric -> NT form)
            launch_gemm(p_Ab, 512, 1, MSZ, p_Ab, 512, 1, MSZ, p_Bb, 512, 1, MSZ,
                        p_Ab, MSZ, 512, 512, 512, ccoef, bcoef, NMAT);
            // X' = a*X + B@X
            launch_gemm(p_Bb, 512, 1, MSZ, Xa, 1, 512, MSZ, Xb, 512, 1, MSZ,
                        Xa, MSZ, 512, 512, 512, 1.f, a, NMAT);
            float* tmp = Xa; Xa = Xb; Xb = tmp;
        }

        k_wupd<<<NMAT * 512, 128>>>(Xa);
    }

    // final forward-only chunk with the last normalized weights
    {
        int cb = NCHUNK * CS;
        const float* qcb = q + (long)cb * DD;
        launch_gemm(p_wc + 2 * WBS, DD, 1, MSZ, qcb, DD, 1, TDS, p_hh, CS, 1, IBS, 0, 0, DI, CS, DD, 1.f, 0.f, BH);
        launch_gemm(p_wc,           DD, 1, MSZ, qcb, DD, 1, TDS, p_g0, CS, 1, IBS, 0, 0, DI, CS, DD, 1.f, 0.f, BH);
        k_ewfwd<<<EW1_N / 256, 256>>>();
        launch_gemm(p_wc + 1 * WBS, DI, 1, MSZ, p_gh, 1, CS, IBS,
                    out + (long)cb * DD, 1, DD, TDS, 0, 0, DD, CS, DI, 1.f, 0.f, BH);
    }
}